// round 9
// baseline (speedup 1.0000x reference)
#include <cuda_runtime.h>
#include <math.h>
#include <stdint.h>

#define B_   32
#define S_   2048
#define D_   400
#define H_   512
#define MS   (B_*S_)
#define MT_  1792              // tensor-role rows per batch; [MT_,2048) = SIMT rows

__device__ float g_q   [(long)MS*H_];
__device__ float g_k   [(long)MS*H_];
__device__ float g_vT  [(long)B_*H_*S_];
__device__ float g_att [(long)B_*S_*S_];
__device__ float g_out [(long)MS*H_];
__device__ float g_proj[(long)MS*D_];
__device__ float g_part[(long)MS*32];     // per-(row, col-chunk) exp partial sums
__device__ float g_WqT [H_*D_];
__device__ float g_WkT [H_*D_];
__device__ float g_WvT [H_*D_];
__device__ float g_WpT [D_*H_];

// ---------------------------------------------------------------------------
__device__ __forceinline__ unsigned f2tf32(float x) {
    unsigned u;
    asm("cvt.rna.tf32.f32 %0, %1;" : "=r"(u) : "f"(x));
    return u;
}

__global__ void transpose_k(const float* __restrict__ in, float* __restrict__ out,
                            int R, int C) {
    int idx = blockIdx.x * blockDim.x + threadIdx.x;
    if (idx < R * C) {
        int r = idx / C, c = idx % C;
        out[c * R + r] = in[idx];
    }
}

#define SMEM_LD 20   // 16 k-floats + 4 pad

// ---------------------------------------------------------------------------
// Plain tensor NT GEMM (R8 core, no softmax hooks): QKV + proj.
// ---------------------------------------------------------------------------
__global__ void __launch_bounds__(256, 2)
gemm_tf32(const float* __restrict__ A, long sA,
          const float* __restrict__ B, long sB,
          float* __restrict__ C, long sC,
          int M, int N, int K, float alpha,
          const float* __restrict__ bias_n,
          const float* __restrict__ bias_m) {
    __shared__ float As[2][128 * SMEM_LD];
    __shared__ float Bs[2][128 * SMEM_LD];

    const int tid  = threadIdx.x;
    const int lane = tid & 31;
    const int wid  = tid >> 5;
    const int wr   = wid & 1;
    const int wc   = wid >> 1;
    const int g    = lane >> 2;
    const int tg   = lane & 3;

    const long bz = blockIdx.z;
    A += bz * sA; B += bz * sB; C += bz * sC;
    const int m0 = blockIdx.y * 128;
    const int n0 = blockIdx.x * 128;

    const int ldr = tid >> 2;
    const int ldc = (tid & 3) * 4;

    const float* Ag0 = A + (long)(m0 + ldr) * K + ldc;
    const float* Ag1 = Ag0 + (long)64 * K;
    const int bn0 = n0 + ldr;
    const bool v0 = bn0 < N, v1 = (bn0 + 64) < N;
    const float* Bg0 = B + (long)(v0 ? bn0 : 0) * K + ldc;
    const float* Bg1 = B + (long)(v1 ? bn0 + 64 : 0) * K + ldc;
    const unsigned z0 = v0 ? 16u : 0u, z1 = v1 ? 16u : 0u;

    unsigned sa[2], sb[2];
    sa[0] = (unsigned)__cvta_generic_to_shared(&As[0][ldr * SMEM_LD + ldc]);
    sa[1] = (unsigned)__cvta_generic_to_shared(&As[1][ldr * SMEM_LD + ldc]);
    sb[0] = (unsigned)__cvta_generic_to_shared(&Bs[0][ldr * SMEM_LD + ldc]);
    sb[1] = (unsigned)__cvta_generic_to_shared(&Bs[1][ldr * SMEM_LD + ldc]);
    const unsigned off64 = 64 * SMEM_LD * 4;

    float acc[4][4][4];
#pragma unroll
    for (int i = 0; i < 4; i++)
#pragma unroll
        for (int j = 0; j < 4; j++)
#pragma unroll
            for (int c = 0; c < 4; c++) acc[i][j][c] = 0.f;

    const int T = K / 16;

    asm volatile("cp.async.cg.shared.global [%0], [%1], 16;\n" :: "r"(sa[0]), "l"(Ag0));
    asm volatile("cp.async.cg.shared.global [%0], [%1], 16;\n" :: "r"(sa[0] + off64), "l"(Ag1));
    asm volatile("cp.async.cg.shared.global [%0], [%1], 16, %2;\n" :: "r"(sb[0]), "l"(Bg0), "r"(z0));
    asm volatile("cp.async.cg.shared.global [%0], [%1], 16, %2;\n" :: "r"(sb[0] + off64), "l"(Bg1), "r"(z1));
    asm volatile("cp.async.commit_group;\n");

    for (int t = 0; t < T; t++) {
        const int buf = t & 1;
        if (t + 1 < T) {
            const int nb = buf ^ 1;
            const long k0 = (long)(t + 1) * 16;
            asm volatile("cp.async.cg.shared.global [%0], [%1], 16;\n" :: "r"(sa[nb]), "l"(Ag0 + k0));
            asm volatile("cp.async.cg.shared.global [%0], [%1], 16;\n" :: "r"(sa[nb] + off64), "l"(Ag1 + k0));
            asm volatile("cp.async.cg.shared.global [%0], [%1], 16, %2;\n" :: "r"(sb[nb]), "l"(Bg0 + k0), "r"(z0));
            asm volatile("cp.async.cg.shared.global [%0], [%1], 16, %2;\n" :: "r"(sb[nb] + off64), "l"(Bg1 + k0), "r"(z1));
            asm volatile("cp.async.commit_group;\n");
            asm volatile("cp.async.wait_group 1;\n");
        } else {
            asm volatile("cp.async.wait_group 0;\n");
        }
        __syncthreads();

#pragma unroll
        for (int kk = 0; kk < 16; kk += 8) {
            unsigned af[4][4], bf[4][2];
#pragma unroll
            for (int i = 0; i < 4; i++) {
                const float* p = &As[buf][(wr * 64 + i * 16 + g) * SMEM_LD + kk + tg];
                af[i][0] = f2tf32(p[0]);
                af[i][1] = f2tf32(p[8 * SMEM_LD]);
                af[i][2] = f2tf32(p[4]);
                af[i][3] = f2tf32(p[8 * SMEM_LD + 4]);
            }
#pragma unroll
            for (int j = 0; j < 4; j++) {
                const float* p = &Bs[buf][(wc * 32 + j * 8 + g) * SMEM_LD + kk + tg];
                bf[j][0] = f2tf32(p[0]);
                bf[j][1] = f2tf32(p[4]);
            }
#pragma unroll
            for (int i = 0; i < 4; i++)
#pragma unroll
                for (int j = 0; j < 4; j++) {
                    asm volatile(
                        "mma.sync.aligned.m16n8k8.row.col.f32.tf32.tf32.f32 "
                        "{%0,%1,%2,%3}, {%4,%5,%6,%7}, {%8,%9}, {%0,%1,%2,%3};\n"
                        : "+f"(acc[i][j][0]), "+f"(acc[i][j][1]),
                          "+f"(acc[i][j][2]), "+f"(acc[i][j][3])
                        : "r"(af[i][0]), "r"(af[i][1]), "r"(af[i][2]), "r"(af[i][3]),
                          "r"(bf[j][0]), "r"(bf[j][1]));
                }
        }
        __syncthreads();
    }

#pragma unroll
    for (int i = 0; i < 4; i++) {
        const int r0 = m0 + wr * 64 + i * 16 + g;
        const int r1 = r0 + 8;
        const float bm0 = bias_m ? bias_m[r0] : 0.f;
        const float bm1 = bias_m ? bias_m[r1] : 0.f;
#pragma unroll
        for (int j = 0; j < 4; j++) {
            const int c0 = n0 + wc * 32 + j * 8 + 2 * tg;
            if (c0 < N) {
                const float bn0 = bias_n ? bias_n[c0]     : 0.f;
                const float bn1 = bias_n ? bias_n[c0 + 1] : 0.f;
                *(float2*)&C[(long)r0 * N + c0] =
                    make_float2(acc[i][j][0] * alpha + bm0 + bn0,
                                acc[i][j][1] * alpha + bm0 + bn1);
                *(float2*)&C[(long)r1 * N + c0] =
                    make_float2(acc[i][j][2] * alpha + bm1 + bn0,
                                acc[i][j][3] * alpha + bm1 + bn1);
            }
        }
    }
}

// ---------------------------------------------------------------------------
// Mixed-pipe GEMM for scores and AV (fused softmax, 32-slot partial layout).
// Blocks [pattern 7:4 per 11 bids]:
//   tensor role: 128x128 tile, rows [0, MT_)  (tf32 mma)
//   simt role:   64x64 tile,  rows [MT_, M)   (fp32 FFMA, exact)
// exp_mode: C = exp(alpha*acc), emit row partials.
// div_mode: C = acc / rowsum (rowsum from partials; tensor rows sum 16 slots,
//           simt rows sum 32 slots).
// ---------------------------------------------------------------------------
__global__ void __launch_bounds__(256, 2)
gemm_mix(const float* __restrict__ A, long sA,
         const float* __restrict__ B, long sB,
         float* __restrict__ C, long sC,
         int M, int N, int K, float alpha,
         float* __restrict__ part_out,
         const float* __restrict__ part_in,
         int tPerZ, int tGx, int sPerZ, int sGx) {
    __shared__ float As[2][128 * SMEM_LD];
    __shared__ float Bs[2][128 * SMEM_LD];
    __shared__ float rcp[128];

    const int tid  = threadIdx.x;
    const int grp = blockIdx.x / 11;
    const int rr  = blockIdx.x % 11;

    if (rr < 7) {
        // ==================== tensor role ====================
        const int tRank = grp * 7 + rr;
        const long z = tRank / tPerZ;
        const int  t = tRank % tPerZ;
        const int m0 = (t / tGx) * 128;
        const int n0 = (t % tGx) * 128;
        const float* Ab = A + z * sA;
        const float* Bb = B + z * sB;
        float* Cb = C + z * sC;

        const int lane = tid & 31;
        const int wid  = tid >> 5;
        const int wr = wid & 1, wc = wid >> 1;
        const int g = lane >> 2, tg = lane & 3;

        if (part_in) {
            float* sc2 = &As[0][0];
            {
                int row = tid >> 1, half = tid & 1;
                const float* pp = part_in + ((long)z * M + m0 + row) * 32 + half * 8;
                sc2[row * 2 + half] = ((pp[0] + pp[1]) + (pp[2] + pp[3]))
                                    + ((pp[4] + pp[5]) + (pp[6] + pp[7]));
            }
            __syncthreads();
            if (tid < 128) rcp[tid] = alpha / (sc2[2 * tid] + sc2[2 * tid + 1]);
            __syncthreads();
        }

        const int ldr = tid >> 2;
        const int ldc = (tid & 3) * 4;
        const float* Ag0 = Ab + (long)(m0 + ldr) * K + ldc;
        const float* Ag1 = Ag0 + (long)64 * K;
        const float* Bg0 = Bb + (long)(n0 + ldr) * K + ldc;
        const float* Bg1 = Bg0 + (long)64 * K;

        unsigned sa[2], sb[2];
        sa[0] = (unsigned)__cvta_generic_to_shared(&As[0][ldr * SMEM_LD + ldc]);
        sa[1] = (unsigned)__cvta_generic_to_shared(&As[1][ldr * SMEM_LD + ldc]);
        sb[0] = (unsigned)__cvta_generic_to_shared(&Bs[0][ldr * SMEM_LD + ldc]);
        sb[1] = (unsigned)__cvta_generic_to_shared(&Bs[1][ldr * SMEM_LD + ldc]);
        const unsigned off64 = 64 * SMEM_LD * 4;

        float acc[4][4][4];
#pragma unroll
        for (int i = 0; i < 4; i++)
#pragma unroll
            for (int j = 0; j < 4; j++)
#pragma unroll
                for (int c = 0; c < 4; c++) acc[i][j][c] = 0.f;

        const int T = K / 16;
        asm volatile("cp.async.cg.shared.global [%0], [%1], 16;\n" :: "r"(sa[0]), "l"(Ag0));
        asm volatile("cp.async.cg.shared.global [%0], [%1], 16;\n" :: "r"(sa[0] + off64), "l"(Ag1));
        asm volatile("cp.async.cg.shared.global [%0], [%1], 16;\n" :: "r"(sb[0]), "l"(Bg0));
        asm volatile("cp.async.cg.shared.global [%0], [%1], 16;\n" :: "r"(sb[0] + off64), "l"(Bg1));
        asm volatile("cp.async.commit_group;\n");

        for (int t2 = 0; t2 < T; t2++) {
            const int buf = t2 & 1;
            if (t2 + 1 < T) {
                const int nb = buf ^ 1;
                const long k0 = (long)(t2 + 1) * 16;
                asm volatile("cp.async.cg.shared.global [%0], [%1], 16;\n" :: "r"(sa[nb]), "l"(Ag0 + k0));
                asm volatile("cp.async.cg.shared.global [%0], [%1], 16;\n" :: "r"(sa[nb] + off64), "l"(Ag1 + k0));
                asm volatile("cp.async.cg.shared.global [%0], [%1], 16;\n" :: "r"(sb[nb]), "l"(Bg0 + k0));
                asm volatile("cp.async.cg.shared.global [%0], [%1], 16;\n" :: "r"(sb[nb] + off64), "l"(Bg1 + k0));
                asm volatile("cp.async.commit_group;\n");
                asm volatile("cp.async.wait_group 1;\n");
            } else {
                asm volatile("cp.async.wait_group 0;\n");
            }
            __syncthreads();

#pragma unroll
            for (int kk = 0; kk < 16; kk += 8) {
                unsigned af[4][4], bf[4][2];
#pragma unroll
                for (int i = 0; i < 4; i++) {
                    const float* p = &As[buf][(wr * 64 + i * 16 + g) * SMEM_LD + kk + tg];
                    af[i][0] = f2tf32(p[0]);
                    af[i][1] = f2tf32(p[8 * SMEM_LD]);
                    af[i][2] = f2tf32(p[4]);
                    af[i][3] = f2tf32(p[8 * SMEM_LD + 4]);
                }
#pragma unroll
                for (int j = 0; j < 4; j++) {
                    const float* p = &Bs[buf][(wc * 32 + j * 8 + g) * SMEM_LD + kk + tg];
                    bf[j][0] = f2tf32(p[0]);
                    bf[j][1] = f2tf32(p[4]);
                }
#pragma unroll
                for (int i = 0; i < 4; i++)
#pragma unroll
                    for (int j = 0; j < 4; j++) {
                        asm volatile(
                            "mma.sync.aligned.m16n8k8.row.col.f32.tf32.tf32.f32 "
                            "{%0,%1,%2,%3}, {%4,%5,%6,%7}, {%8,%9}, {%0,%1,%2,%3};\n"
                            : "+f"(acc[i][j][0]), "+f"(acc[i][j][1]),
                              "+f"(acc[i][j][2]), "+f"(acc[i][j][3])
                            : "r"(af[i][0]), "r"(af[i][1]), "r"(af[i][2]), "r"(af[i][3]),
                              "r"(bf[j][0]), "r"(bf[j][1]));
                    }
            }
            __syncthreads();
        }

        float* sred = &As[0][0];
#pragma unroll
        for (int i = 0; i < 4; i++) {
            const int r0loc = wr * 64 + i * 16 + g;
            const int r1loc = r0loc + 8;
            const int r0 = m0 + r0loc, r1 = m0 + r1loc;
            float f0 = alpha, f1 = alpha;
            if (part_in) { f0 = rcp[r0loc]; f1 = rcp[r1loc]; }
            float s0 = 0.f, s1 = 0.f;
#pragma unroll
            for (int j = 0; j < 4; j++) {
                const int c0 = n0 + wc * 32 + j * 8 + 2 * tg;
                float v00 = acc[i][j][0] * f0;
                float v01 = acc[i][j][1] * f0;
                float v10 = acc[i][j][2] * f1;
                float v11 = acc[i][j][3] * f1;
                if (part_out) {
                    v00 = __expf(v00); v01 = __expf(v01);
                    v10 = __expf(v10); v11 = __expf(v11);
                    s0 += v00 + v01;  s1 += v10 + v11;
                }
                *(float2*)&Cb[(long)r0 * N + c0] = make_float2(v00, v01);
                *(float2*)&Cb[(long)r1 * N + c0] = make_float2(v10, v11);
            }
            if (part_out) {
                s0 += __shfl_xor_sync(~0u, s0, 1);  s0 += __shfl_xor_sync(~0u, s0, 2);
                s1 += __shfl_xor_sync(~0u, s1, 1);  s1 += __shfl_xor_sync(~0u, s1, 2);
                if (tg == 0) {
                    sred[wc * 128 + r0loc] = s0;
                    sred[wc * 128 + r1loc] = s1;
                }
            }
        }
        if (part_out) {
            __syncthreads();
            if (tid < 128) {
                float p = (sred[tid] + sred[128 + tid])
                        + (sred[256 + tid] + sred[384 + tid]);
                part_out[((long)z * M + m0 + tid) * 32 + (t % tGx)] = p;
            }
        }
    } else {
        // ==================== simt role (exact fp32) ====================
        const int sRank = grp * 4 + (rr - 7);
        const long z = sRank / sPerZ;
        const int  t = sRank % sPerZ;
        const int sy = t / sGx, sx = t % sGx;
        const int m0 = MT_ + sy * 64;
        const int n0 = sx * 64;
        const float* Ab = A + z * sA;
        const float* Bb = B + z * sB;
        float* Cb = C + z * sC;

        float* As2 = &As[0][0];           // [16][68]
        float* Bs2 = &As[0][16 * 68];     // [16][68]

        if (part_in) {
            float* scr = &Bs[0][0];
            {
                int row = tid >> 2, q = tid & 3;
                const float* pp = part_in + ((long)z * M + m0 + row) * 32 + q * 8;
                scr[tid] = ((pp[0] + pp[1]) + (pp[2] + pp[3]))
                         + ((pp[4] + pp[5]) + (pp[6] + pp[7]));
            }
            __syncthreads();
            if (tid < 64)
                rcp[tid] = 1.f / ((scr[4 * tid] + scr[4 * tid + 1])
                                + (scr[4 * tid + 2] + scr[4 * tid + 3]));
            __syncthreads();
        }

        const int lr = tid >> 2;
        const int lc = (tid & 3) * 4;
        const int ty = tid >> 4;
        const int tx = tid & 15;
        const float* Ap = Ab + (long)(m0 + lr) * K + lc;
        const float* Bp = Bb + (long)(n0 + lr) * K + lc;

        float acc[4][4];
#pragma unroll
        for (int i = 0; i < 4; i++)
#pragma unroll
            for (int j = 0; j < 4; j++) acc[i][j] = 0.f;

        for (int k0 = 0; k0 < K; k0 += 16) {
            float4 av = *(const float4*)(Ap + k0);
            float4 bv = *(const float4*)(Bp + k0);
            As2[(lc + 0) * 68 + lr] = av.x; As2[(lc + 1) * 68 + lr] = av.y;
            As2[(lc + 2) * 68 + lr] = av.z; As2[(lc + 3) * 68 + lr] = av.w;
            Bs2[(lc + 0) * 68 + lr] = bv.x; Bs2[(lc + 1) * 68 + lr] = bv.y;
            Bs2[(lc + 2) * 68 + lr] = bv.z; Bs2[(lc + 3) * 68 + lr] = bv.w;
            __syncthreads();
#pragma unroll
            for (int k = 0; k < 16; k++) {
                float4 a4 = *(const float4*)&As2[k * 68 + ty * 4];
                float4 b4 = *(const float4*)&Bs2[k * 68 + tx * 4];
                float ar[4] = {a4.x, a4.y, a4.z, a4.w};
                float br[4] = {b4.x, b4.y, b4.z, b4.w};
#pragma unroll
                for (int i = 0; i < 4; i++)
#pragma unroll
                    for (int j = 0; j < 4; j++) acc[i][j] += ar[i] * br[j];
            }
            __syncthreads();
        }

        if (part_out) {
            // exp + 64-col row partial sums
            float rs[4];
#pragma unroll
            for (int i = 0; i < 4; i++) {
                float s = 0.f;
#pragma unroll
                for (int j = 0; j < 4; j++) {
                    float v = __expf(acc[i][j] * alpha);
                    acc[i][j] = v;
                    s += v;
                }
                s += __shfl_xor_sync(~0u, s, 1);
                s += __shfl_xor_sync(~0u, s, 2);
                s += __shfl_xor_sync(~0u, s, 4);
                s += __shfl_xor_sync(~0u, s, 8);
                rs[i] = s;   // valid on tx==0 lanes
            }
            if (tx == 0) {
#pragma unroll
                for (int i = 0; i < 4; i++) rcp[ty * 4 + i] = rs[i];
            }
            __syncthreads();
            if (tid < 64)
                part_out[((long)z * M + m0 + tid) * 32 + sx] = rcp[tid];
        }

#pragma unroll
        for (int i = 0; i < 4; i++) {
            const int row = m0 + ty * 4 + i;
            float f = alpha;
            if (part_in) f = rcp[ty * 4 + i];
            if (part_out) f = 1.f;
#pragma unroll
            for (int j = 0; j < 4; j += 2) {
                const int col = n0 + tx * 4 + j;
                *(float2*)&Cb[(long)row * N + col] =
                    make_float2(acc[i][j] * f, acc[i][j + 1] * f);
            }
        }
    }
}

// ---------------------------------------------------------------------------
__global__ void __launch_bounds__(128)
ln_epilogue(const float* __restrict__ proj, const float* __restrict__ rgb,
            const float* __restrict__ gate, const float* __restrict__ gamma,
            const float* __restrict__ beta, float* __restrict__ out) {
    const long row = blockIdx.x;
    const int tid = threadIdx.x;
    const float g = gate[0];
    __shared__ float xs[D_];
    __shared__ float red[4];

    float s = 0.f;
    for (int i = tid; i < D_; i += 128) {
        float x = rgb[row * D_ + i] + g * proj[row * D_ + i];
        xs[i] = x;
        s += x;
    }
#pragma unroll
    for (int o = 16; o > 0; o >>= 1) s += __shfl_xor_sync(~0u, s, o);
    if ((tid & 31) == 0) red[tid >> 5] = s;
    __syncthreads();
    float mu = (red[0] + red[1] + red[2] + red[3]) * (1.0f / D_);
    __syncthreads();

    float vs = 0.f;
    for (int i = tid; i < D_; i += 128) {
        float d = xs[i] - mu;
        vs += d * d;
    }
#pragma unroll
    for (int o = 16; o > 0; o >>= 1) vs += __shfl_xor_sync(~0u, vs, o);
    if ((tid & 31) == 0) red[tid >> 5] = vs;
    __syncthreads();
    float var = (red[0] + red[1] + red[2] + red[3]) * (1.0f / D_);
    float inv = rsqrtf(var + 1e-5f);

    for (int i = tid; i < D_; i += 128) {
        out[row * D_ + i] = (xs[i] - mu) * inv * gamma[i] + beta[i];
    }
}

// ---------------------------------------------------------------------------
static float* sym(const void* s) {
    void* p = nullptr;
    cudaGetSymbolAddress(&p, s);
    return (float*)p;
}

extern "C" void kernel_launch(void* const* d_in, const int* in_sizes, int n_in,
                              void* d_out, int out_size) {
    const float* rgb   = (const float*)d_in[0];
    const float* pose  = (const float*)d_in[1];
    const float* Wq    = (const float*)d_in[2];
    const float* bq    = (const float*)d_in[3];
    const float* Wk    = (const float*)d_in[4];
    const float* bk    = (const float*)d_in[5];
    const float* Wv    = (const float*)d_in[6];
    const float* bv    = (const float*)d_in[7];
    const float* Wp    = (const float*)d_in[8];
    const float* bp    = (const float*)d_in[9];
    const float* gamma = (const float*)d_in[10];
    const float* beta  = (const float*)d_in[11];
    const float* gate  = (const float*)d_in[12];
    float* out = (float*)d_out;

    float* q    = sym(g_q);    float* k    = sym(g_k);
    float* vT   = sym(g_vT);   float* att  = sym(g_att);
    float* o    = sym(g_out);  float* proj = sym(g_proj);
    float* part = sym(g_part);
    float* WqT  = sym(g_WqT);  float* WkT  = sym(g_WkT);
    float* WvT  = sym(g_WvT);  float* WpT  = sym(g_WpT);

    const float inv_sqrt_h = 0.044194173824159216f;

    {
        int n1 = D_ * H_;
        transpose_k<<<(n1 + 255) / 256, 256>>>(Wq, WqT, D_, H_);
        transpose_k<<<(n1 + 255) / 256, 256>>>(Wk, WkT, D_, H_);
        transpose_k<<<(n1 + 255) / 256, 256>>>(Wv, WvT, D_, H_);
        transpose_k<<<(n1 + 255) / 256, 256>>>(Wp, WpT, H_, D_);
    }

    // q = rgb @ Wq + bq
    gemm_tf32<<<dim3(H_ / 128, MS / 128, 1), 256>>>(
        rgb, 0, WqT, 0, q, 0, MS, H_, D_, 1.f, bq, nullptr);
    // k = pose @ Wk + bk
    gemm_tf32<<<dim3(H_ / 128, MS / 128, 1), 256>>>(
        pose, 0, WkT, 0, k, 0, MS, H_, D_, 1.f, bk, nullptr);
    // vT[b][h][s] = (pose_b @ Wv + bv)^T
    gemm_tf32<<<dim3(S_ / 128, H_ / 128, B_), 256>>>(
        WvT, 0, pose, (long)S_ * D_, vT, (long)H_ * S_,
        H_, S_, D_, 1.f, nullptr, bv);

    // att = exp(q k^T / sqrt(H)) + partials  [mixed pipes]
    // tensor: 224/batch (14x16), simt: 128/batch (4x32) -> groups = 1024
    gemm_mix<<<1024 * 11, 256>>>(
        q, (long)S_ * H_, k, (long)S_ * H_, att, (long)S_ * S_,
        S_, S_, H_, inv_sqrt_h, part, nullptr, 224, 16, 128, 32);

    // out = (att @ v) / rowsum  [mixed pipes]
    // tensor: 56/batch (14x4), simt: 32/batch (4x8) -> groups = 256
    gemm_mix<<<256 * 11, 256>>>(
        att, (long)S_ * S_, vT, (long)H_ * S_, o, (long)S_ * H_,
        S_, H_, S_, 1.f, nullptr, part, 56, 4, 32, 8);

    // proj = out @ Wp + bp  (N=400 tail guarded)
    gemm_tf32<<<dim3((D_ + 127) / 128, MS / 128, 1), 256>>>(
        o, 0, WpT, 0, proj, 0, MS, D_, H_, 1.f, bp, nullptr);

    ln_epilogue<<<B_ * S_, 128>>>(proj, rgb, gate, gamma, beta, out);
}

// round 11
// speedup vs baseline: 1.4324x; 1.4324x over previous
#include <cuda_runtime.h>
#include <math.h>
#include <stdint.h>

#define B_   32
#define S_   2048
#define D_   400
#define H_   512
#define MS   (B_*S_)

__device__ float g_t    [(long)MS*D_];      // rgb @ M
__device__ float g_att  [(long)B_*S_*S_];   // exp(scores)
__device__ float g_poseT[(long)B_*D_*S_];   // pose transposed per batch
__device__ float g_ap   [(long)MS*D_];      // attn @ pose
__device__ float g_proj [(long)MS*D_];
__device__ float g_part [(long)MS*16];
__device__ float g_MT   [D_*D_];            // MT[n][d] = (WqWk^T)[d][n]
__device__ float g_GT   [D_*D_];            // GT[n][d] = (WvWp)[d][n]
__device__ float g_WpT  [D_*H_];
__device__ float g_w1   [D_];               // Wq @ bk
__device__ float g_w2   [D_];               // Wk @ bq
__device__ float g_d0   [D_];               // bv @ Wp + bp
__device__ float g_c0   [1];                // bq . bk
__device__ float g_bm   [MS];               // (rgb_i.w1 + c0) * inv_sqrt_h
__device__ float g_bn   [MS];               // (pose_j.w2) * inv_sqrt_h

// ---------------------------------------------------------------------------
__device__ __forceinline__ unsigned f2tf32(float x) {
    unsigned u;
    asm("cvt.rna.tf32.f32 %0, %1;" : "=r"(u) : "f"(x));
    return u;
}

__global__ void transpose_k(const float* __restrict__ in, float* __restrict__ out,
                            int R, int C) {
    int idx = blockIdx.x * blockDim.x + threadIdx.x;
    if (idx < R * C) {
        int r = idx / C, c = idx % C;
        out[c * R + r] = in[idx];
    }
}

// batched tiled transpose: in [B][S][D] -> out [B][D][S]
__global__ void transpose_bt(const float* __restrict__ in, float* __restrict__ out) {
    __shared__ float tile[32][33];
    const int b  = blockIdx.z;
    const int j0 = blockIdx.x * 32;
    const int d0 = blockIdx.y * 32;
    {
        int d = d0 + threadIdx.x;
        for (int r = threadIdx.y; r < 32; r += 8) {
            int j = j0 + r;
            tile[r][threadIdx.x] = (d < D_) ? in[((long)b * S_ + j) * D_ + d] : 0.f;
        }
    }
    __syncthreads();
    {
        int j = j0 + threadIdx.x;
        for (int r = threadIdx.y; r < 32; r += 8) {
            int dd = d0 + r;
            if (dd < D_) out[((long)b * D_ + dd) * S_ + j] = tile[threadIdx.x][r];
        }
    }
}

// ---------------------------------------------------------------------------
// Exact fp32 SIMT NT product for small weight matrices:
// C[m][n] = sum_h A[m][h]*B[n][h];  tile 64x64x16; M,N guarded; K%16==0.
// ---------------------------------------------------------------------------
__global__ void __launch_bounds__(256)
wprod(const float* __restrict__ A, const float* __restrict__ B,
      float* __restrict__ C, int M, int N, int K) {
    __shared__ float As[16][68];
    __shared__ float Bs[16][68];

    const int tid = threadIdx.x;
    const int m0 = blockIdx.y * 64;
    const int n0 = blockIdx.x * 64;
    const int lr = tid >> 2;
    const int lc = (tid & 3) * 4;
    const int ty = tid >> 4;
    const int tx = tid & 15;

    const bool aok = (m0 + lr) < M;
    const bool bok = (n0 + lr) < N;
    const float* Aptr = A + (long)(aok ? m0 + lr : 0) * K + lc;
    const float* Bptr = B + (long)(bok ? n0 + lr : 0) * K + lc;

    float acc[4][4];
#pragma unroll
    for (int i = 0; i < 4; i++)
#pragma unroll
        for (int j = 0; j < 4; j++) acc[i][j] = 0.f;

    for (int k0 = 0; k0 < K; k0 += 16) {
        float4 av = aok ? *(const float4*)(Aptr + k0) : make_float4(0, 0, 0, 0);
        float4 bv = bok ? *(const float4*)(Bptr + k0) : make_float4(0, 0, 0, 0);
        As[lc + 0][lr] = av.x; As[lc + 1][lr] = av.y;
        As[lc + 2][lr] = av.z; As[lc + 3][lr] = av.w;
        Bs[lc + 0][lr] = bv.x; Bs[lc + 1][lr] = bv.y;
        Bs[lc + 2][lr] = bv.z; Bs[lc + 3][lr] = bv.w;
        __syncthreads();
#pragma unroll
        for (int k = 0; k < 16; k++) {
            float4 a4 = *(const float4*)&As[k][ty * 4];
            float4 b4 = *(const float4*)&Bs[k][tx * 4];
            float ar[4] = {a4.x, a4.y, a4.z, a4.w};
            float br[4] = {b4.x, b4.y, b4.z, b4.w};
#pragma unroll
            for (int i = 0; i < 4; i++)
#pragma unroll
                for (int j = 0; j < 4; j++) acc[i][j] += ar[i] * br[j];
        }
        __syncthreads();
    }

#pragma unroll
    for (int i = 0; i < 4; i++) {
        int row = m0 + ty * 4 + i;
        if (row < M) {
#pragma unroll
            for (int j = 0; j < 4; j++) {
                int col = n0 + tx * 4 + j;
                if (col < N) C[(long)row * N + col] = acc[i][j];
            }
        }
    }
}

// ---------------------------------------------------------------------------
// small bias vectors: w1 = Wq@bk, w2 = Wk@bq, d0 = bv@Wp + bp, c0 = bq.bk
// ---------------------------------------------------------------------------
__global__ void prep_vec(const float* __restrict__ Wq, const float* __restrict__ Wk,
                         const float* __restrict__ Wp, const float* __restrict__ bq,
                         const float* __restrict__ bk, const float* __restrict__ bv,
                         const float* __restrict__ bp,
                         float* __restrict__ w1, float* __restrict__ w2,
                         float* __restrict__ d0, float* __restrict__ c0) {
    int t = threadIdx.x;
    if (t < D_) {
        float s1 = 0.f, s2 = 0.f, s3 = 0.f;
#pragma unroll 4
        for (int h = 0; h < H_; h++) {
            s1 += Wq[t * H_ + h] * bk[h];
            s2 += Wk[t * H_ + h] * bq[h];
            s3 += bv[h] * Wp[h * D_ + t];
        }
        w1[t] = s1; w2[t] = s2; d0[t] = s3 + bp[t];
    } else if (t == 511) {
        float s = 0.f;
        for (int h = 0; h < H_; h++) s += bq[h] * bk[h];
        c0[0] = s;
    }
}

// ---------------------------------------------------------------------------
// bm[i] = (rgb_i . w1 + c0)*inv_s ; bn[j] = (pose_j . w2)*inv_s. Warp per row.
// ---------------------------------------------------------------------------
__global__ void rowdot(const float* __restrict__ rgb, const float* __restrict__ pose,
                       const float* __restrict__ w1, const float* __restrict__ w2,
                       const float* __restrict__ c0, float inv_s,
                       float* __restrict__ bm, float* __restrict__ bn) {
    long r = (long)blockIdx.x * 8 + (threadIdx.x >> 5);
    const int lane = threadIdx.x & 31;
    const bool isPose = r >= MS;
    const long row = isPose ? r - MS : r;
    const float* x = (isPose ? pose : rgb) + row * D_;
    const float* w = isPose ? w2 : w1;

    float s = 0.f;
    for (int c = lane * 4; c < D_; c += 128) {
        float4 xv = *(const float4*)(x + c);
        float4 wv = *(const float4*)(w + c);
        s += xv.x * wv.x + xv.y * wv.y + xv.z * wv.z + xv.w * wv.w;
    }
#pragma unroll
    for (int o = 16; o > 0; o >>= 1) s += __shfl_xor_sync(~0u, s, o);
    if (lane == 0) {
        if (isPose) bn[row] = s * inv_s;
        else        bm[row] = (s + c0[0]) * inv_s;
    }
}

#define SMEM_LD 20   // 16 k-floats + 4 pad

// ---------------------------------------------------------------------------
// Tensor NT GEMM (tf32 mma m16n8k8) with fused-softmax hooks + strided biases.
// C[m][n] = alpha*sum_k A[m][k]*B[n][k] (+bias_m[z*sBm+m]) (+bias_n[z*sBn+n])
// part_out: C = exp(...), emit 128-col partial row sums to slot blockIdx.x (16).
// part_in : factor = alpha / rowsum(16 partials).
// Block 128x128x16, 256 thr; M%128==0, K%16==0; N tail guarded+zfilled.
// ---------------------------------------------------------------------------
__global__ void __launch_bounds__(256, 2)
gemm_tf32(const float* __restrict__ A, long sA,
          const float* __restrict__ B, long sB,
          float* __restrict__ C, long sC,
          int M, int N, int K, float alpha,
          const float* __restrict__ bias_n, long sBn,
          const float* __restrict__ bias_m, long sBm,
          float* __restrict__ part_out,
          const float* __restrict__ part_in) {
    __shared__ float As[2][128 * SMEM_LD];
    __shared__ float Bs[2][128 * SMEM_LD];
    __shared__ float rcp[128];

    const int tid  = threadIdx.x;
    const int lane = tid & 31;
    const int wid  = tid >> 5;
    const int wr   = wid & 1;
    const int wc   = wid >> 1;
    const int g    = lane >> 2;
    const int tg   = lane & 3;

    const long bz = blockIdx.z;
    A += bz * sA; B += bz * sB; C += bz * sC;
    const int m0 = blockIdx.y * 128;
    const int n0 = blockIdx.x * 128;

    if (part_in) {
        float* sc2 = &As[0][0];
        {
            int row = tid >> 1, half = tid & 1;
            const float* pp = part_in + ((long)bz * M + m0 + row) * 16 + half * 8;
            sc2[row * 2 + half] = ((pp[0] + pp[1]) + (pp[2] + pp[3]))
                                + ((pp[4] + pp[5]) + (pp[6] + pp[7]));
        }
        __syncthreads();
        if (tid < 128) rcp[tid] = alpha / (sc2[2 * tid] + sc2[2 * tid + 1]);
        __syncthreads();
    }

    const int ldr = tid >> 2;
    const int ldc = (tid & 3) * 4;

    const float* Ag0 = A + (long)(m0 + ldr) * K + ldc;
    const float* Ag1 = Ag0 + (long)64 * K;
    const int bn0 = n0 + ldr;
    const bool v0 = bn0 < N, v1 = (bn0 + 64) < N;
    const float* Bg0 = B + (long)(v0 ? bn0 : 0) * K + ldc;
    const float* Bg1 = B + (long)(v1 ? bn0 + 64 : 0) * K + ldc;
    const unsigned z0 = v0 ? 16u : 0u, z1 = v1 ? 16u : 0u;

    unsigned sa[2], sb[2];
    sa[0] = (unsigned)__cvta_generic_to_shared(&As[0][ldr * SMEM_LD + ldc]);
    sa[1] = (unsigned)__cvta_generic_to_shared(&As[1][ldr * SMEM_LD + ldc]);
    sb[0] = (unsigned)__cvta_generic_to_shared(&Bs[0][ldr * SMEM_LD + ldc]);
    sb[1] = (unsigned)__cvta_generic_to_shared(&Bs[1][ldr * SMEM_LD + ldc]);
    const unsigned off64 = 64 * SMEM_LD * 4;

    float acc[4][4][4];
#pragma unroll
    for (int i = 0; i < 4; i++)
#pragma unroll
        for (int j = 0; j < 4; j++)
#pragma unroll
            for (int c = 0; c < 4; c++) acc[i][j][c] = 0.f;

    const int T = K / 16;

    asm volatile("cp.async.cg.shared.global [%0], [%1], 16;\n" :: "r"(sa[0]), "l"(Ag0));
    asm volatile("cp.async.cg.shared.global [%0], [%1], 16;\n" :: "r"(sa[0] + off64), "l"(Ag1));
    asm volatile("cp.async.cg.shared.global [%0], [%1], 16, %2;\n" :: "r"(sb[0]), "l"(Bg0), "r"(z0));
    asm volatile("cp.async.cg.shared.global [%0], [%1], 16, %2;\n" :: "r"(sb[0] + off64), "l"(Bg1), "r"(z1));
    asm volatile("cp.async.commit_group;\n");

    for (int t = 0; t < T; t++) {
        const int buf = t & 1;
        if (t + 1 < T) {
            const int nb = buf ^ 1;
            const long k0 = (long)(t + 1) * 16;
            asm volatile("cp.async.cg.shared.global [%0], [%1], 16;\n" :: "r"(sa[nb]), "l"(Ag0 + k0));
            asm volatile("cp.async.cg.shared.global [%0], [%1], 16;\n" :: "r"(sa[nb] + off64), "l"(Ag1 + k0));
            asm volatile("cp.async.cg.shared.global [%0], [%1], 16, %2;\n" :: "r"(sb[nb]), "l"(Bg0 + k0), "r"(z0));
            asm volatile("cp.async.cg.shared.global [%0], [%1], 16, %2;\n" :: "r"(sb[nb] + off64), "l"(Bg1 + k0), "r"(z1));
            asm volatile("cp.async.commit_group;\n");
            asm volatile("cp.async.wait_group 1;\n");
        } else {
            asm volatile("cp.async.wait_group 0;\n");
        }
        __syncthreads();

#pragma unroll
        for (int kk = 0; kk < 16; kk += 8) {
            unsigned af[4][4], bf[4][2];
#pragma unroll
            for (int i = 0; i < 4; i++) {
                const float* p = &As[buf][(wr * 64 + i * 16 + g) * SMEM_LD + kk + tg];
                af[i][0] = f2tf32(p[0]);
                af[i][1] = f2tf32(p[8 * SMEM_LD]);
                af[i][2] = f2tf32(p[4]);
                af[i][3] = f2tf32(p[8 * SMEM_LD + 4]);
            }
#pragma unroll
            for (int j = 0; j < 4; j++) {
                const float* p = &Bs[buf][(wc * 32 + j * 8 + g) * SMEM_LD + kk + tg];
                bf[j][0] = f2tf32(p[0]);
                bf[j][1] = f2tf32(p[4]);
            }
#pragma unroll
            for (int i = 0; i < 4; i++)
#pragma unroll
                for (int j = 0; j < 4; j++) {
                    asm volatile(
                        "mma.sync.aligned.m16n8k8.row.col.f32.tf32.tf32.f32 "
                        "{%0,%1,%2,%3}, {%4,%5,%6,%7}, {%8,%9}, {%0,%1,%2,%3};\n"
                        : "+f"(acc[i][j][0]), "+f"(acc[i][j][1]),
                          "+f"(acc[i][j][2]), "+f"(acc[i][j][3])
                        : "r"(af[i][0]), "r"(af[i][1]), "r"(af[i][2]), "r"(af[i][3]),
                          "r"(bf[j][0]), "r"(bf[j][1]));
                }
        }
        __syncthreads();
    }

    float* sred = &As[0][0];

#pragma unroll
    for (int i = 0; i < 4; i++) {
        const int r0loc = wr * 64 + i * 16 + g;
        const int r1loc = r0loc + 8;
        const int r0 = m0 + r0loc, r1 = m0 + r1loc;
        float f0 = alpha, f1 = alpha;
        if (part_in) { f0 = rcp[r0loc]; f1 = rcp[r1loc]; }
        const float bm0 = bias_m ? bias_m[bz * sBm + r0] : 0.f;
        const float bm1 = bias_m ? bias_m[bz * sBm + r1] : 0.f;
        float s0 = 0.f, s1 = 0.f;
#pragma unroll
        for (int j = 0; j < 4; j++) {
            const int c0 = n0 + wc * 32 + j * 8 + 2 * tg;
            if (c0 < N) {
                const float bn0v = bias_n ? bias_n[bz * sBn + c0]     : 0.f;
                const float bn1v = bias_n ? bias_n[bz * sBn + c0 + 1] : 0.f;
                float v00 = acc[i][j][0] * f0 + bm0 + bn0v;
                float v01 = acc[i][j][1] * f0 + bm0 + bn1v;
                float v10 = acc[i][j][2] * f1 + bm1 + bn0v;
                float v11 = acc[i][j][3] * f1 + bm1 + bn1v;
                if (part_out) {
                    v00 = __expf(v00); v01 = __expf(v01);
                    v10 = __expf(v10); v11 = __expf(v11);
                    s0 += v00 + v01;  s1 += v10 + v11;
                }
                *(float2*)&C[(long)r0 * N + c0] = make_float2(v00, v01);
                *(float2*)&C[(long)r1 * N + c0] = make_float2(v10, v11);
            }
        }
        if (part_out) {
            s0 += __shfl_xor_sync(~0u, s0, 1);  s0 += __shfl_xor_sync(~0u, s0, 2);
            s1 += __shfl_xor_sync(~0u, s1, 1);  s1 += __shfl_xor_sync(~0u, s1, 2);
            if (tg == 0) {
                sred[wc * 128 + r0loc] = s0;
                sred[wc * 128 + r1loc] = s1;
            }
        }
    }

    if (part_out) {
        __syncthreads();
        if (tid < 128) {
            float p = (sred[tid] + sred[128 + tid])
                    + (sred[256 + tid] + sred[384 + tid]);
            part_out[((long)bz * M + m0 + tid) * 16 + blockIdx.x] = p;
        }
    }
}

// ---------------------------------------------------------------------------
__global__ void __launch_bounds__(128)
ln_epilogue(const float* __restrict__ proj, const float* __restrict__ rgb,
            const float* __restrict__ gate, const float* __restrict__ gamma,
            const float* __restrict__ beta, float* __restrict__ out) {
    const long row = blockIdx.x;
    const int tid = threadIdx.x;
    const float g = gate[0];
    __shared__ float xs[D_];
    __shared__ float red[4];

    float s = 0.f;
    for (int i = tid; i < D_; i += 128) {
        float x = rgb[row * D_ + i] + g * proj[row * D_ + i];
        xs[i] = x;
        s += x;
    }
#pragma unroll
    for (int o = 16; o > 0; o >>= 1) s += __shfl_xor_sync(~0u, s, o);
    if ((tid & 31) == 0) red[tid >> 5] = s;
    __syncthreads();
    float mu = (red[0] + red[1] + red[2] + red[3]) * (1.0f / D_);
    __syncthreads();

    float vs = 0.f;
    for (int i = tid; i < D_; i += 128) {
        float d = xs[i] - mu;
        vs += d * d;
    }
#pragma unroll
    for (int o = 16; o > 0; o >>= 1) vs += __shfl_xor_sync(~0u, vs, o);
    if ((tid & 31) == 0) red[tid >> 5] = vs;
    __syncthreads();
    float var = (red[0] + red[1] + red[2] + red[3]) * (1.0f / D_);
    float inv = rsqrtf(var + 1e-5f);

    for (int i = tid; i < D_; i += 128) {
        out[row * D_ + i] = (xs[i] - mu) * inv * gamma[i] + beta[i];
    }
}

// ---------------------------------------------------------------------------
static float* sym(const void* s) {
    void* p = nullptr;
    cudaGetSymbolAddress(&p, s);
    return (float*)p;
}

extern "C" void kernel_launch(void* const* d_in, const int* in_sizes, int n_in,
                              void* d_out, int out_size) {
    const float* rgb   = (const float*)d_in[0];
    const float* pose  = (const float*)d_in[1];
    const float* Wq    = (const float*)d_in[2];
    const float* bq    = (const float*)d_in[3];
    const float* Wk    = (const float*)d_in[4];
    const float* bk    = (const float*)d_in[5];
    const float* Wv    = (const float*)d_in[6];
    const float* bv    = (const float*)d_in[7];
    const float* Wp    = (const float*)d_in[8];
    const float* bp    = (const float*)d_in[9];
    const float* gamma = (const float*)d_in[10];
    const float* beta  = (const float*)d_in[11];
    const float* gate  = (const float*)d_in[12];
    float* out = (float*)d_out;

    float* t     = sym(g_t);     float* att  = sym(g_att);
    float* poseT = sym(g_poseT); float* ap   = sym(g_ap);
    float* proj  = sym(g_proj);  float* part = sym(g_part);
    float* MT    = sym(g_MT);    float* GT   = sym(g_GT);
    float* WpT   = sym(g_WpT);
    float* w1    = sym(g_w1);    float* w2   = sym(g_w2);
    float* d0    = sym(g_d0);    float* c0   = sym(g_c0);
    float* bm    = sym(g_bm);    float* bn   = sym(g_bn);

    const float inv_sqrt_h = 0.044194173824159216f;  // 1/sqrt(512)

    // ---- weight algebra (exact fp32) ----
    transpose_k<<<(H_ * D_ + 255) / 256, 256>>>(Wp, WpT, H_, D_);   // WpT[d][h]
    // MT[n][d] = sum_h Wk[n,h]*Wq[d,h]  ( = (WqWk^T)^T )
    wprod<<<dim3(7, 7), 256>>>(Wk, Wq, MT, D_, D_, H_);
    // GT[n][d] = sum_h WpT[n,h]*Wv[d,h] ( = (WvWp)^T )
    wprod<<<dim3(7, 7), 256>>>(WpT, Wv, GT, D_, D_, H_);
    prep_vec<<<1, 512>>>(Wq, Wk, Wp, bq, bk, bv, bp, w1, w2, d0, c0);
    rowdot<<<2 * MS / 8, 256>>>(rgb, pose, w1, w2, c0, inv_sqrt_h, bm, bn);
    transpose_bt<<<dim3(S_ / 32, (D_ + 31) / 32, B_), dim3(32, 8)>>>(pose, poseT);

    // t = rgb @ M  (B = MT, N=400 tail)
    gemm_tf32<<<dim3((D_ + 127) / 128, MS / 128, 1), 256>>>(
        rgb, 0, MT, 0, t, 0, MS, D_, D_, 1.f,
        nullptr, 0, nullptr, 0, nullptr, nullptr);

    // att = exp((t.pose_j + bm_i + bn_j))  + partial sums  (alpha = 1/sqrt(H))
    gemm_tf32<<<dim3(S_ / 128, S_ / 128, B_), 256>>>(
        t, (long)S_ * D_, pose, (long)S_ * D_, att, (long)S_ * S_,
        S_, S_, D_, inv_sqrt_h, bn, S_, bm, S_, part, nullptr);

    // ap = (att @ pose) / rowsum   (B = poseT, N=400 tail)
    gemm_tf32<<<dim3((D_ + 127) / 128, S_ / 128, B_), 256>>>(
        att, (long)S_ * S_, poseT, (long)D_ * S_, ap, (long)S_ * D_,
        S_, D_, S_, 1.f, nullptr, 0, nullptr, 0, nullptr, part);

    // proj = ap @ G + d0  (B = GT, bias_n = d0; attn absorbed bv exactly)
    gemm_tf32<<<dim3((D_ + 127) / 128, MS / 128, 1), 256>>>(
        ap, 0, GT, 0, proj, 0, MS, D_, D_, 1.f,
        d0, 0, nullptr, 0, nullptr, nullptr);

    // fused = LN(rgb + gate*proj)
    ln_epilogue<<<MS, 128>>>(proj, rgb, gate, gamma, beta, out);
}

// round 14
// speedup vs baseline: 1.5701x; 1.0961x over previous
#include <cuda_runtime.h>
#include <math.h>
#include <stdint.h>

#define B_   32
#define S_   2048
#define D_   400
#define H_   512
#define MS   (B_*S_)

__device__ float g_t    [(long)MS*D_];      // rgb @ M
__device__ float g_att  [(long)B_*S_*S_];   // exp(scores)
__device__ float g_poseT[(long)B_*D_*S_];   // pose transposed per batch
__device__ float g_ap   [(long)MS*D_];      // attn @ pose
__device__ float g_proj [(long)MS*D_];
__device__ float g_part [(long)MS*16];
__device__ float g_MT   [D_*D_];            // MT[n][d] = (WqWk^T)[d][n]
__device__ float g_GT   [D_*D_];            // GT[n][d] = (WvWp)[d][n]
__device__ float g_WpT  [D_*H_];
__device__ float g_w1   [D_];               // Wq @ bk
__device__ float g_w2   [D_];               // Wk @ bq
__device__ float g_d0   [D_];               // bv @ Wp + bp
__device__ float g_c0   [1];                // bq . bk
__device__ float g_bm   [MS];               // (rgb_i.w1 + c0) * inv_sqrt_h
__device__ float g_bn   [MS];               // (pose_j.w2) * inv_sqrt_h

// ---------------------------------------------------------------------------
__device__ __forceinline__ unsigned f2tf32(float x) {
    unsigned u;
    asm("cvt.rna.tf32.f32 %0, %1;" : "=r"(u) : "f"(x));
    return u;
}

__global__ void transpose_k(const float* __restrict__ in, float* __restrict__ out,
                            int R, int C) {
    int idx = blockIdx.x * blockDim.x + threadIdx.x;
    if (idx < R * C) {
        int r = idx / C, c = idx % C;
        out[c * R + r] = in[idx];
    }
}

// batched tiled transpose: in [B][S][D] -> out [B][D][S]
__global__ void transpose_bt(const float* __restrict__ in, float* __restrict__ out) {
    __shared__ float tile[32][33];
    const int b  = blockIdx.z;
    const int j0 = blockIdx.x * 32;
    const int d0 = blockIdx.y * 32;
    {
        int d = d0 + threadIdx.x;
        for (int r = threadIdx.y; r < 32; r += 8) {
            int j = j0 + r;
            tile[r][threadIdx.x] = (d < D_) ? in[((long)b * S_ + j) * D_ + d] : 0.f;
        }
    }
    __syncthreads();
    {
        int j = j0 + threadIdx.x;
        for (int r = threadIdx.y; r < 32; r += 8) {
            int dd = d0 + r;
            if (dd < D_) out[((long)b * D_ + dd) * S_ + j] = tile[threadIdx.x][r];
        }
    }
}

// ---------------------------------------------------------------------------
// Exact fp32 SIMT NT product for small weight matrices:
// C[m][n] = sum_h A[m][h]*B[n][h];  tile 64x64x16; M,N guarded; K%16==0.
// ---------------------------------------------------------------------------
__global__ void __launch_bounds__(256)
wprod(const float* __restrict__ A, const float* __restrict__ B,
      float* __restrict__ C, int M, int N, int K) {
    __shared__ float As[16][68];
    __shared__ float Bs[16][68];

    const int tid = threadIdx.x;
    const int m0 = blockIdx.y * 64;
    const int n0 = blockIdx.x * 64;
    const int lr = tid >> 2;
    const int lc = (tid & 3) * 4;
    const int ty = tid >> 4;
    const int tx = tid & 15;

    const bool aok = (m0 + lr) < M;
    const bool bok = (n0 + lr) < N;
    const float* Aptr = A + (long)(aok ? m0 + lr : 0) * K + lc;
    const float* Bptr = B + (long)(bok ? n0 + lr : 0) * K + lc;

    float acc[4][4];
#pragma unroll
    for (int i = 0; i < 4; i++)
#pragma unroll
        for (int j = 0; j < 4; j++) acc[i][j] = 0.f;

    for (int k0 = 0; k0 < K; k0 += 16) {
        float4 av = aok ? *(const float4*)(Aptr + k0) : make_float4(0, 0, 0, 0);
        float4 bv = bok ? *(const float4*)(Bptr + k0) : make_float4(0, 0, 0, 0);
        As[lc + 0][lr] = av.x; As[lc + 1][lr] = av.y;
        As[lc + 2][lr] = av.z; As[lc + 3][lr] = av.w;
        Bs[lc + 0][lr] = bv.x; Bs[lc + 1][lr] = bv.y;
        Bs[lc + 2][lr] = bv.z; Bs[lc + 3][lr] = bv.w;
        __syncthreads();
#pragma unroll
        for (int k = 0; k < 16; k++) {
            float4 a4 = *(const float4*)&As[k][ty * 4];
            float4 b4 = *(const float4*)&Bs[k][tx * 4];
            float ar[4] = {a4.x, a4.y, a4.z, a4.w};
            float br[4] = {b4.x, b4.y, b4.z, b4.w};
#pragma unroll
            for (int i = 0; i < 4; i++)
#pragma unroll
                for (int j = 0; j < 4; j++) acc[i][j] += ar[i] * br[j];
        }
        __syncthreads();
    }

#pragma unroll
    for (int i = 0; i < 4; i++) {
        int row = m0 + ty * 4 + i;
        if (row < M) {
#pragma unroll
            for (int j = 0; j < 4; j++) {
                int col = n0 + tx * 4 + j;
                if (col < N) C[(long)row * N + col] = acc[i][j];
            }
        }
    }
}

// ---------------------------------------------------------------------------
// bias vectors, warp-per-row: w1 = Wq@bk, w2 = Wk@bq, d0 = bv@Wp + bp,
// c0 = bq.bk. Grid: 51 blocks x 256 thr (8 warps); warp r in [0,400) handles
// row r; warp 400 computes c0.
// ---------------------------------------------------------------------------
__global__ void __launch_bounds__(256)
prep_vec(const float* __restrict__ Wq, const float* __restrict__ Wk,
         const float* __restrict__ Wp, const float* __restrict__ bq,
         const float* __restrict__ bk, const float* __restrict__ bv,
         const float* __restrict__ bp,
         float* __restrict__ w1, float* __restrict__ w2,
         float* __restrict__ d0, float* __restrict__ c0) {
    const int w = blockIdx.x * 8 + (threadIdx.x >> 5);
    const int lane = threadIdx.x & 31;

    if (w < D_) {
        float s1 = 0.f, s2 = 0.f, s3 = 0.f;
        for (int h = lane * 4; h < H_; h += 128) {
            float4 q4 = *(const float4*)(Wq + (long)w * H_ + h);
            float4 k4 = *(const float4*)(Wk + (long)w * H_ + h);
            float4 bk4 = *(const float4*)(bk + h);
            float4 bq4 = *(const float4*)(bq + h);
            float4 bv4 = *(const float4*)(bv + h);
            s1 += q4.x * bk4.x + q4.y * bk4.y + q4.z * bk4.z + q4.w * bk4.w;
            s2 += k4.x * bq4.x + k4.y * bq4.y + k4.z * bq4.z + k4.w * bq4.w;
            s3 += bv4.x * Wp[(h + 0) * D_ + w] + bv4.y * Wp[(h + 1) * D_ + w]
                + bv4.z * Wp[(h + 2) * D_ + w] + bv4.w * Wp[(h + 3) * D_ + w];
        }
#pragma unroll
        for (int o = 16; o > 0; o >>= 1) {
            s1 += __shfl_xor_sync(~0u, s1, o);
            s2 += __shfl_xor_sync(~0u, s2, o);
            s3 += __shfl_xor_sync(~0u, s3, o);
        }
        if (lane == 0) { w1[w] = s1; w2[w] = s2; d0[w] = s3 + bp[w]; }
    } else if (w == D_) {
        float s = 0.f;
        for (int h = lane * 4; h < H_; h += 128) {
            float4 q4 = *(const float4*)(bq + h);
            float4 k4 = *(const float4*)(bk + h);
            s += q4.x * k4.x + q4.y * k4.y + q4.z * k4.z + q4.w * k4.w;
        }
#pragma unroll
        for (int o = 16; o > 0; o >>= 1) s += __shfl_xor_sync(~0u, s, o);
        if (lane == 0) c0[0] = s;
    }
}

// ---------------------------------------------------------------------------
// bm[i] = (rgb_i . w1 + c0)*inv_s ; bn[j] = (pose_j . w2)*inv_s. Warp per row.
// ---------------------------------------------------------------------------
__global__ void rowdot(const float* __restrict__ rgb, const float* __restrict__ pose,
                       const float* __restrict__ w1, const float* __restrict__ w2,
                       const float* __restrict__ c0, float inv_s,
                       float* __restrict__ bm, float* __restrict__ bn) {
    long r = (long)blockIdx.x * 8 + (threadIdx.x >> 5);
    const int lane = threadIdx.x & 31;
    const bool isPose = r >= MS;
    const long row = isPose ? r - MS : r;
    const float* x = (isPose ? pose : rgb) + row * D_;
    const float* w = isPose ? w2 : w1;

    float s = 0.f;
    for (int c = lane * 4; c < D_; c += 128) {
        float4 xv = *(const float4*)(x + c);
        float4 wv = *(const float4*)(w + c);
        s += xv.x * wv.x + xv.y * wv.y + xv.z * wv.z + xv.w * wv.w;
    }
#pragma unroll
    for (int o = 16; o > 0; o >>= 1) s += __shfl_xor_sync(~0u, s, o);
    if (lane == 0) {
        if (isPose) bn[row] = s * inv_s;
        else        bm[row] = (s + c0[0]) * inv_s;
    }
}

#define SMEM_LD 20   // 16 k-floats + 4 pad

// ---------------------------------------------------------------------------
// Tensor NT GEMM (tf32 mma m16n8k8) with fused-softmax hooks + strided biases.
// C[m][n] = alpha*sum_k A[m][k]*B[n][k] (+bias_m[z*sBm+m]) (+bias_n[z*sBn+n])
// part_out: C = exp(...), emit 128-col partial row sums to slot blockIdx.x (16).
// part_in : factor = alpha / rowsum(16 partials).
// Block 128x128x16, 256 thr; M%128==0, K%16==0; N tail guarded+zfilled.
// ---------------------------------------------------------------------------
__global__ void __launch_bounds__(256, 2)
gemm_tf32(const float* __restrict__ A, long sA,
          const float* __restrict__ B, long sB,
          float* __restrict__ C, long sC,
          int M, int N, int K, float alpha,
          const float* __restrict__ bias_n, long sBn,
          const float* __restrict__ bias_m, long sBm,
          float* __restrict__ part_out,
          const float* __restrict__ part_in) {
    __shared__ float As[2][128 * SMEM_LD];
    __shared__ float Bs[2][128 * SMEM_LD];
    __shared__ float rcp[128];

    const int tid  = threadIdx.x;
    const int lane = tid & 31;
    const int wid  = tid >> 5;
    const int wr   = wid & 1;
    const int wc   = wid >> 1;
    const int g    = lane >> 2;
    const int tg   = lane & 3;

    const long bz = blockIdx.z;
    A += bz * sA; B += bz * sB; C += bz * sC;
    const int m0 = blockIdx.y * 128;
    const int n0 = blockIdx.x * 128;

    if (part_in) {
        float* sc2 = &As[0][0];
        {
            int row = tid >> 1, half = tid & 1;
            const float* pp = part_in + ((long)bz * M + m0 + row) * 16 + half * 8;
            sc2[row * 2 + half] = ((pp[0] + pp[1]) + (pp[2] + pp[3]))
                                + ((pp[4] + pp[5]) + (pp[6] + pp[7]));
        }
        __syncthreads();
        if (tid < 128) rcp[tid] = alpha / (sc2[2 * tid] + sc2[2 * tid + 1]);
        __syncthreads();
    }

    const int ldr = tid >> 2;
    const int ldc = (tid & 3) * 4;

    const float* Ag0 = A + (long)(m0 + ldr) * K + ldc;
    const float* Ag1 = Ag0 + (long)64 * K;
    const int bn0 = n0 + ldr;
    const bool v0 = bn0 < N, v1 = (bn0 + 64) < N;
    const float* Bg0 = B + (long)(v0 ? bn0 : 0) * K + ldc;
    const float* Bg1 = B + (long)(v1 ? bn0 + 64 : 0) * K + ldc;
    const unsigned z0 = v0 ? 16u : 0u, z1 = v1 ? 16u : 0u;

    unsigned sa[2], sb[2];
    sa[0] = (unsigned)__cvta_generic_to_shared(&As[0][ldr * SMEM_LD + ldc]);
    sa[1] = (unsigned)__cvta_generic_to_shared(&As[1][ldr * SMEM_LD + ldc]);
    sb[0] = (unsigned)__cvta_generic_to_shared(&Bs[0][ldr * SMEM_LD + ldc]);
    sb[1] = (unsigned)__cvta_generic_to_shared(&Bs[1][ldr * SMEM_LD + ldc]);
    const unsigned off64 = 64 * SMEM_LD * 4;

    float acc[4][4][4];
#pragma unroll
    for (int i = 0; i < 4; i++)
#pragma unroll
        for (int j = 0; j < 4; j++)
#pragma unroll
            for (int c = 0; c < 4; c++) acc[i][j][c] = 0.f;

    const int T = K / 16;

    asm volatile("cp.async.cg.shared.global [%0], [%1], 16;\n" :: "r"(sa[0]), "l"(Ag0));
    asm volatile("cp.async.cg.shared.global [%0], [%1], 16;\n" :: "r"(sa[0] + off64), "l"(Ag1));
    asm volatile("cp.async.cg.shared.global [%0], [%1], 16, %2;\n" :: "r"(sb[0]), "l"(Bg0), "r"(z0));
    asm volatile("cp.async.cg.shared.global [%0], [%1], 16, %2;\n" :: "r"(sb[0] + off64), "l"(Bg1), "r"(z1));
    asm volatile("cp.async.commit_group;\n");

    for (int t = 0; t < T; t++) {
        const int buf = t & 1;
        if (t + 1 < T) {
            const int nb = buf ^ 1;
            const long k0 = (long)(t + 1) * 16;
            asm volatile("cp.async.cg.shared.global [%0], [%1], 16;\n" :: "r"(sa[nb]), "l"(Ag0 + k0));
            asm volatile("cp.async.cg.shared.global [%0], [%1], 16;\n" :: "r"(sa[nb] + off64), "l"(Ag1 + k0));
            asm volatile("cp.async.cg.shared.global [%0], [%1], 16, %2;\n" :: "r"(sb[nb]), "l"(Bg0 + k0), "r"(z0));
            asm volatile("cp.async.cg.shared.global [%0], [%1], 16, %2;\n" :: "r"(sb[nb] + off64), "l"(Bg1 + k0), "r"(z1));
            asm volatile("cp.async.commit_group;\n");
            asm volatile("cp.async.wait_group 1;\n");
        } else {
            asm volatile("cp.async.wait_group 0;\n");
        }
        __syncthreads();

#pragma unroll
        for (int kk = 0; kk < 16; kk += 8) {
            unsigned af[4][4], bf[4][2];
#pragma unroll
            for (int i = 0; i < 4; i++) {
                const float* p = &As[buf][(wr * 64 + i * 16 + g) * SMEM_LD + kk + tg];
                af[i][0] = f2tf32(p[0]);
                af[i][1] = f2tf32(p[8 * SMEM_LD]);
                af[i][2] = f2tf32(p[4]);
                af[i][3] = f2tf32(p[8 * SMEM_LD + 4]);
            }
#pragma unroll
            for (int j = 0; j < 4; j++) {
                const float* p = &Bs[buf][(wc * 32 + j * 8 + g) * SMEM_LD + kk + tg];
                bf[j][0] = f2tf32(p[0]);
                bf[j][1] = f2tf32(p[4]);
            }
#pragma unroll
            for (int i = 0; i < 4; i++)
#pragma unroll
                for (int j = 0; j < 4; j++) {
                    asm volatile(
                        "mma.sync.aligned.m16n8k8.row.col.f32.tf32.tf32.f32 "
                        "{%0,%1,%2,%3}, {%4,%5,%6,%7}, {%8,%9}, {%0,%1,%2,%3};\n"
                        : "+f"(acc[i][j][0]), "+f"(acc[i][j][1]),
                          "+f"(acc[i][j][2]), "+f"(acc[i][j][3])
                        : "r"(af[i][0]), "r"(af[i][1]), "r"(af[i][2]), "r"(af[i][3]),
                          "r"(bf[j][0]), "r"(bf[j][1]));
                }
        }
        __syncthreads();
    }

    float* sred = &As[0][0];

#pragma unroll
    for (int i = 0; i < 4; i++) {
        const int r0loc = wr * 64 + i * 16 + g;
        const int r1loc = r0loc + 8;
        const int r0 = m0 + r0loc, r1 = m0 + r1loc;
        float f0 = alpha, f1 = alpha;
        if (part_in) { f0 = rcp[r0loc]; f1 = rcp[r1loc]; }
        const float bm0 = bias_m ? bias_m[bz * sBm + r0] : 0.f;
        const float bm1 = bias_m ? bias_m[bz * sBm + r1] : 0.f;
        float s0 = 0.f, s1 = 0.f;
#pragma unroll
        for (int j = 0; j < 4; j++) {
            const int c0 = n0 + wc * 32 + j * 8 + 2 * tg;
            if (c0 < N) {
                const float bn0v = bias_n ? bias_n[bz * sBn + c0]     : 0.f;
                const float bn1v = bias_n ? bias_n[bz * sBn + c0 + 1] : 0.f;
                float v00 = acc[i][j][0] * f0 + bm0 + bn0v;
                float v01 = acc[i][j][1] * f0 + bm0 + bn1v;
                float v10 = acc[i][j][2] * f1 + bm1 + bn0v;
                float v11 = acc[i][j][3] * f1 + bm1 + bn1v;
                if (part_out) {
                    v00 = __expf(v00); v01 = __expf(v01);
                    v10 = __expf(v10); v11 = __expf(v11);
                    s0 += v00 + v01;  s1 += v10 + v11;
                }
                *(float2*)&C[(long)r0 * N + c0] = make_float2(v00, v01);
                *(float2*)&C[(long)r1 * N + c0] = make_float2(v10, v11);
            }
        }
        if (part_out) {
            s0 += __shfl_xor_sync(~0u, s0, 1);  s0 += __shfl_xor_sync(~0u, s0, 2);
            s1 += __shfl_xor_sync(~0u, s1, 1);  s1 += __shfl_xor_sync(~0u, s1, 2);
            if (tg == 0) {
                sred[wc * 128 + r0loc] = s0;
                sred[wc * 128 + r1loc] = s1;
            }
        }
    }

    if (part_out) {
        __syncthreads();
        if (tid < 128) {
            float p = (sred[tid] + sred[128 + tid])
                    + (sred[256 + tid] + sred[384 + tid]);
            part_out[((long)bz * M + m0 + tid) * 16 + blockIdx.x] = p;
        }
    }
}

// ---------------------------------------------------------------------------
__global__ void __launch_bounds__(128)
ln_epilogue(const float* __restrict__ proj, const float* __restrict__ rgb,
            const float* __restrict__ gate, const float* __restrict__ gamma,
            const float* __restrict__ beta, float* __restrict__ out) {
    const long row = blockIdx.x;
    const int tid = threadIdx.x;
    const float g = gate[0];
    __shared__ float xs[D_];
    __shared__ float red[4];

    float s = 0.f;
    for (int i = tid; i < D_; i += 128) {
        float x = rgb[row * D_ + i] + g * proj[row * D_ + i];
        xs[i] = x;
        s += x;
    }
#pragma unroll
    for (int o = 16; o > 0; o >>= 1) s += __shfl_xor_sync(~0u, s, o);
    if ((tid & 31) == 0) red[tid >> 5] = s;
    __syncthreads();
    float mu = (red[0] + red[1] + red[2] + red[3]) * (1.0f / D_);
    __syncthreads();

    float vs = 0.f;
    for (int i = tid; i < D_; i += 128) {
        float d = xs[i] - mu;
        vs += d * d;
    }
#pragma unroll
    for (int o = 16; o > 0; o >>= 1) vs += __shfl_xor_sync(~0u, vs, o);
    if ((tid & 31) == 0) red[tid >> 5] = vs;
    __syncthreads();
    float var = (red[0] + red[1] + red[2] + red[3]) * (1.0f / D_);
    float inv = rsqrtf(var + 1e-5f);

    for (int i = tid; i < D_; i += 128) {
        out[row * D_ + i] = (xs[i] - mu) * inv * gamma[i] + beta[i];
    }
}

// ---------------------------------------------------------------------------
static float* sym(const void* s) {
    void* p = nullptr;
    cudaGetSymbolAddress(&p, s);
    return (float*)p;
}

extern "C" void kernel_launch(void* const* d_in, const int* in_sizes, int n_in,
                              void* d_out, int out_size) {
    const float* rgb   = (const float*)d_in[0];
    const float* pose  = (const float*)d_in[1];
    const float* Wq    = (const float*)d_in[2];
    const float* bq    = (const float*)d_in[3];
    const float* Wk    = (const float*)d_in[4];
    const float* bk    = (const float*)d_in[5];
    const float* Wv    = (const float*)d_in[6];
    const float* bv    = (const float*)d_in[7];
    const float* Wp    = (const float*)d_in[8];
    const float* bp    = (const float*)d_in[9];
    const float* gamma = (const float*)d_in[10];
    const float* beta  = (const float*)d_in[11];
    const float* gate  = (const float*)d_in[12];
    float* out = (float*)d_out;

    float* t     = sym(g_t);     float* att  = sym(g_att);
    float* poseT = sym(g_poseT); float* ap   = sym(g_ap);
    float* proj  = sym(g_proj);  float* part = sym(g_part);
    float* MT    = sym(g_MT);    float* GT   = sym(g_GT);
    float* WpT   = sym(g_WpT);
    float* w1    = sym(g_w1);    float* w2   = sym(g_w2);
    float* d0    = sym(g_d0);    float* c0   = sym(g_c0);
    float* bm    = sym(g_bm);    float* bn   = sym(g_bn);

    const float inv_sqrt_h = 0.044194173824159216f;  // 1/sqrt(512)

    // ---- weight algebra (exact fp32) ----
    transpose_k<<<(H_ * D_ + 255) / 256, 256>>>(Wp, WpT, H_, D_);   // WpT[d][h]
    // MT[n][d] = sum_h Wk[n,h]*Wq[d,h]  ( = (WqWk^T)^T )
    wprod<<<dim3(7, 7), 256>>>(Wk, Wq, MT, D_, D_, H_);
    // GT[n][d] = sum_h WpT[n,h]*Wv[d,h] ( = (WvWp)^T )
    wprod<<<dim3(7, 7), 256>>>(WpT, Wv, GT, D_, D_, H_);
    prep_vec<<<51, 256>>>(Wq, Wk, Wp, bq, bk, bv, bp, w1, w2, d0, c0);
    rowdot<<<2 * MS / 8, 256>>>(rgb, pose, w1, w2, c0, inv_sqrt_h, bm, bn);
    transpose_bt<<<dim3(S_ / 32, (D_ + 31) / 32, B_), dim3(32, 8)>>>(pose, poseT);

    // t = rgb @ M  (B = MT, N=400 tail)
    gemm_tf32<<<dim3((D_ + 127) / 128, MS / 128, 1), 256>>>(
        rgb, 0, MT, 0, t, 0, MS, D_, D_, 1.f,
        nullptr, 0, nullptr, 0, nullptr, nullptr);

    // att = exp((t.pose_j + bm_i + bn_j))  + partial sums  (alpha = 1/sqrt(H))
    gemm_tf32<<<dim3(S_ / 128, S_ / 128, B_), 256>>>(
        t, (long)S_ * D_, pose, (long)S_ * D_, att, (long)S_ * S_,
        S_, S_, D_, inv_sqrt_h, bn, S_, bm, S_, part, nullptr);

    // ap = (att @ pose) / rowsum   (B = poseT, N=400 tail)
    gemm_tf32<<<dim3((D_ + 127) / 128, S_ / 128, B_), 256>>>(
        att, (long)S_ * S_, poseT, (long)D_ * S_, ap, (long)S_ * D_,
        S_, D_, S_, 1.f, nullptr, 0, nullptr, 0, nullptr, part);

    // proj = ap @ G + d0  (B = GT, bias_n = d0; attn absorbed bv exactly)
    gemm_tf32<<<dim3((D_ + 127) / 128, MS / 128, 1), 256>>>(
        ap, 0, GT, 0, proj, 0, MS, D_, D_, 1.f,
        d0, 0, nullptr, 0, nullptr, nullptr);

    // fused = LN(rgb + gate*proj)
    ln_epilogue<<<MS, 128>>>(proj, rgb, gate, gamma, beta, out);
}